// round 16
// baseline (speedup 1.0000x reference)
#include <cuda_runtime.h>
#include <cuda_fp16.h>
#include <math.h>
#include <stdint.h>

#define NB 4
#define NS 2048
#define ND 1024
#define NH 4096
#define NE 8
#define NTOK (NB*NS)      /* 8192 tokens */
#define NPAIR (NTOK*2)    /* 16384 (token,expert) pairs */

#define TM 128
#define TN 128
#define KC 64               /* K per stage (64 halfs = 128 B rows) */
#define NSTG 3
#define ROWB 144            /* padded row: 128 B data + 16 B pad */
#define ABYTES (128*ROWB)   /* 18432 B per matrix per stage */
#define STGB (2*ABYTES)
#define SOFF 512
#define DSMEM (SOFF + NSTG*STGB)   /* 111104 B -> 2 CTAs/SM */

// ---------------- device scratch (static allocations only) ----------------
__device__ float g_M[ND*NE];
__device__ float g_cvec[NE];
__device__ float g_qv[NE];
__device__ int   g_cnt[NE];
__device__ int   g_list[NE][NTOK];
__device__ float g_gate[NPAIR];
__device__ __half g_xh[(size_t)NTOK*ND];      // fp16 x (written by router)
__device__ __half g_W1t[(size_t)NE*NH*ND];    // W1^T  [e][n][k], fp16
__device__ __half g_W2t[(size_t)NE*ND*NH];    // W2^T  [e][n][k], fp16
__device__ __half g_h[(size_t)NPAIR*NH];      // hidden acts, fp16
__device__ float g_imp[NE];
__device__ float g_rz;
__device__ float g_ent;

// ---------------- helpers ----------------
__device__ __forceinline__ uint32_t smem_u32(const void* p) {
    uint32_t a;
    asm("{ .reg .u64 t; cvta.to.shared.u64 t, %1; cvt.u32.u64 %0, t; }"
        : "=r"(a) : "l"(p));
    return a;
}
__device__ __forceinline__ void cp16(uint32_t dst, const void* src, uint32_t bytes) {
    asm volatile("cp.async.cg.shared.global [%0], [%1], 16, %2;\n"
                 :: "r"(dst), "l"(src), "r"(bytes) : "memory");
}
#define CP_COMMIT() asm volatile("cp.async.commit_group;\n" ::: "memory")
#define CP_WAIT1()  asm volatile("cp.async.wait_group 1;\n" ::: "memory")
#define CP_WAIT0()  asm volatile("cp.async.wait_group 0;\n" ::: "memory")

__device__ __forceinline__ void mma_f16(float* c, const uint32_t* a, const uint32_t* b) {
    asm volatile("mma.sync.aligned.m16n8k16.row.col.f32.f16.f16.f32 "
        "{%0,%1,%2,%3}, {%4,%5,%6,%7}, {%8,%9}, {%0,%1,%2,%3};"
        : "+f"(c[0]), "+f"(c[1]), "+f"(c[2]), "+f"(c[3])
        : "r"(a[0]), "r"(a[1]), "r"(a[2]), "r"(a[3]), "r"(b[0]), "r"(b[1]));
}
__device__ __forceinline__ void ldsm4(uint32_t* r, uint32_t a) {
    asm volatile("ldmatrix.sync.aligned.m8n8.x4.shared.b16 {%0,%1,%2,%3}, [%4];"
        : "=r"(r[0]), "=r"(r[1]), "=r"(r[2]), "=r"(r[3]) : "r"(a));
}

// ---------------- prep reductions ----------------
__device__ __forceinline__ float blk_sum(float v, float* sred) {
    int tid = threadIdx.x;
    sred[tid] = v;
    __syncthreads();
    #pragma unroll
    for (int o = 128; o > 0; o >>= 1) {
        if (tid < o) sred[tid] += sred[tid + o];
        __syncthreads();
    }
    float r = sred[0];
    __syncthreads();
    return r;
}

#define T1_BLKS (NE*(ND/64)*(NH/32))   /* 16384 */
#define T2_BLKS (NE*(NH/64)*(ND/32))   /* 16384 */

__global__ __launch_bounds__(256) void prep_kernel(
        const float* __restrict__ ctx_W, const float* __restrict__ r_W,
        const float* __restrict__ ctx_b, const float* __restrict__ q_W,
        const float* __restrict__ q_b,  const float* __restrict__ r_b) {
    __shared__ float sred[256];
    int b = blockIdx.x;
    int tid = threadIdx.x;
    if (b == 0) {
        if (tid < NE) { g_cnt[tid] = 0; g_imp[tid] = 0.f; }
        if (tid == 0) { g_rz = 0.f; g_ent = 0.f; }
        float pc[NE], pq[NE];
        #pragma unroll
        for (int e = 0; e < NE; e++) { pc[e] = 0.f; pq[e] = 0.f; }
        for (int d = tid; d < ND; d += 256) {
            float cb = ctx_b[d] + q_b[d];
            float qw = q_W[d];
            #pragma unroll
            for (int e = 0; e < NE; e++) {
                pc[e] += cb * r_W[d*NE + e];
                pq[e] += qw * r_W[d*NE + e];
            }
        }
        #pragma unroll
        for (int e = 0; e < NE; e++) {
            float vc = blk_sum(pc[e], sred);
            float vq = blk_sum(pq[e], sred);
            if (tid == 0) { g_cvec[e] = vc + r_b[e]; g_qv[e] = vq; }
        }
    } else {
        int j = b - 1;
        float part[NE];
        #pragma unroll
        for (int e = 0; e < NE; e++) part[e] = 0.f;
        for (int d = tid; d < ND; d += 256) {
            float w = ctx_W[(size_t)j*ND + d];
            #pragma unroll
            for (int e = 0; e < NE; e++) part[e] += w * r_W[d*NE + e];
        }
        #pragma unroll
        for (int e = 0; e < NE; e++) {
            float v = blk_sum(part[e], sred);
            if (tid == 0) g_M[j*NE + e] = v;
        }
    }
}

// ---------------- transposes (64 S-rows x 32 S-cols tile) ----------------
__device__ __forceinline__ void transpose_tile(const float* S, __half* D,
                                               int R, int C, int r0, int c0,
                                               int tid) {
    __shared__ float t[64][33];
    int lane = tid & 31, w = tid >> 5;
    #pragma unroll
    for (int i = 0; i < 8; i++)
        t[w*8 + i][lane] = S[(size_t)(r0 + w*8 + i)*C + c0 + lane];
    __syncthreads();
    #pragma unroll
    for (int jj = 0; jj < 4; jj++) {
        int j = w + jj*8;
        __half2 v = __floats2half2_rn(t[2*lane][j], t[2*lane + 1][j]);
        *(__half2*)(D + (size_t)(c0 + j)*R + r0 + 2*lane) = v;
    }
}

__global__ __launch_bounds__(256) void transpose_w1(const float* __restrict__ W1) {
    int i = blockIdx.x;
    int e = i >> 11;
    int rem = i & 2047;         // 128 cblk x 16 rblk (R=ND=1024, C=NH)
    int c0 = (rem & 127) * 32;
    int r0 = (rem >> 7) * 64;
    transpose_tile(W1 + (size_t)e*ND*NH, g_W1t + (size_t)e*ND*NH,
                   ND, NH, r0, c0, threadIdx.x);
}

__global__ __launch_bounds__(256) void transpose_w2(const float* __restrict__ W2) {
    int i = blockIdx.x;
    int e = i >> 11;
    int rem = i & 2047;         // 32 cblk x 64 rblk (R=NH=4096, C=ND)
    int c0 = (rem & 31) * 32;
    int r0 = (rem >> 5) * 64;
    transpose_tile(W2 + (size_t)e*NH*ND, g_W2t + (size_t)e*NH*ND,
                   NH, ND, r0, c0, threadIdx.x);
}

// ---------------- router: one warp per token; also zeroes out[] ----------------
__global__ __launch_bounds__(256) void router_kernel(
        const float* __restrict__ x, const float* __restrict__ ctx,
        const float* __restrict__ quality,
        const float* __restrict__ rn_g, const float* __restrict__ rn_b,
        const float* __restrict__ cn_g, const float* __restrict__ cn_b,
        const float* __restrict__ r_W, const float* __restrict__ temp_p,
        float* __restrict__ out) {
    int wid = threadIdx.x >> 5, lane = threadIdx.x & 31;
    int t = blockIdx.x*8 + wid;

    {
        float4 z = make_float4(0.f,0.f,0.f,0.f);
        float4* op = (float4*)(out + (size_t)t*ND);
        #pragma unroll
        for (int i = 0; i < 8; i++) op[lane + 32*i] = z;
    }

    const float4* xr = (const float4*)(x   + (size_t)t*ND);
    const float4* cr = (const float4*)(ctx + (size_t)t*ND);
    float4 xv[8], cv[8];
    #pragma unroll
    for (int i = 0; i < 8; i++) { xv[i] = xr[lane + 32*i]; cv[i] = cr[lane + 32*i]; }

    #pragma unroll
    for (int i = 0; i < 8; i++) {
        __half2 h0 = __floats2half2_rn(xv[i].x, xv[i].y);
        __half2 h1 = __floats2half2_rn(xv[i].z, xv[i].w);
        uint2 o = make_uint2(*(uint32_t*)&h0, *(uint32_t*)&h1);
        *(uint2*)(g_xh + (size_t)t*ND + (lane + 32*i)*4) = o;
    }

    float sx=0.f, sxx=0.f, sc=0.f, scc=0.f;
    #pragma unroll
    for (int i = 0; i < 8; i++) {
        sx  += xv[i].x + xv[i].y + xv[i].z + xv[i].w;
        sxx += xv[i].x*xv[i].x + xv[i].y*xv[i].y + xv[i].z*xv[i].z + xv[i].w*xv[i].w;
        sc  += cv[i].x + cv[i].y + cv[i].z + cv[i].w;
        scc += cv[i].x*cv[i].x + cv[i].y*cv[i].y + cv[i].z*cv[i].z + cv[i].w*cv[i].w;
    }
    #pragma unroll
    for (int o = 16; o; o >>= 1) {
        sx  += __shfl_xor_sync(0xFFFFFFFFu, sx,  o);
        sxx += __shfl_xor_sync(0xFFFFFFFFu, sxx, o);
        sc  += __shfl_xor_sync(0xFFFFFFFFu, sc,  o);
        scc += __shfl_xor_sync(0xFFFFFFFFu, scc, o);
    }
    float mu_x = sx*(1.f/ND), mu_c = sc*(1.f/ND);
    float rs_x = rsqrtf(sxx*(1.f/ND) - mu_x*mu_x + 1e-5f);
    float rs_c = rsqrtf(scc*(1.f/ND) - mu_c*mu_c + 1e-5f);

    float part[NE];
    #pragma unroll
    for (int e = 0; e < NE; e++) part[e] = 0.f;
    #pragma unroll
    for (int i = 0; i < 8; i++) {
        float xa[4] = {xv[i].x, xv[i].y, xv[i].z, xv[i].w};
        float ca[4] = {cv[i].x, cv[i].y, cv[i].z, cv[i].w};
        #pragma unroll
        for (int j = 0; j < 4; j++) {
            int d = (lane + 32*i)*4 + j;
            float nx = (xa[j]-mu_x)*rs_x*rn_g[d] + rn_b[d];
            float nc = (ca[j]-mu_c)*rs_c*cn_g[d] + cn_b[d];
            const float* rw = r_W + d*NE;
            const float* mm = g_M + d*NE;
            #pragma unroll
            for (int e = 0; e < NE; e++) part[e] += nx*rw[e] + nc*mm[e];
        }
    }
    #pragma unroll
    for (int e = 0; e < NE; e++)
        #pragma unroll
        for (int o = 16; o; o >>= 1)
            part[e] += __shfl_xor_sync(0xFFFFFFFFu, part[e], o);

    __shared__ float simp[8][NE];
    __shared__ float srz[8];
    __shared__ float sent[8];

    if (lane == 0) {
        float temp = fmaxf(temp_p[0], 0.25f);
        float q = quality[t / NS];
        float lg[NE];
        #pragma unroll
        for (int e = 0; e < NE; e++)
            lg[e] = (part[e] + g_cvec[e] + q*g_qv[e]) / temp;

        int i1 = 0;
        #pragma unroll
        for (int e = 1; e < NE; e++) if (lg[e] > lg[i1]) i1 = e;
        int i2 = (i1 == 0) ? 1 : 0;
        #pragma unroll
        for (int e = 0; e < NE; e++) {
            if (e == i1 || e == i2) continue;
            if (lg[e] > lg[i2]) i2 = e;
        }

        float mx = lg[0];
        #pragma unroll
        for (int e = 1; e < NE; e++) mx = fmaxf(mx, lg[e]);
        float se = 0.f;
        #pragma unroll
        for (int e = 0; e < NE; e++) se += expf(lg[e]-mx);
        float lse = mx + logf(se);
        float inv_se = 1.f/se;
        float ent = 0.f;
        #pragma unroll
        for (int e = 0; e < NE; e++) {
            float p = expf(lg[e]-mx)*inv_se;
            simp[wid][e] = p;
            ent -= p * (lg[e]-lse);
        }
        srz[wid]  = lse*lse;
        sent[wid] = ent;

        float ex = expf(lg[i2]-lg[i1]);
        float inv = 1.f/(1.f+ex);
        g_gate[2*t]   = inv;
        g_gate[2*t+1] = ex*inv;
        int p1 = atomicAdd(&g_cnt[i1], 1);
        g_list[i1][p1] = 2*t;
        int p2 = atomicAdd(&g_cnt[i2], 1);
        g_list[i2][p2] = 2*t+1;
    }
    __syncthreads();
    int tid = threadIdx.x;
    if (tid < NE) {
        float s = 0.f;
        #pragma unroll
        for (int w = 0; w < 8; w++) s += simp[w][tid];
        atomicAdd(&g_imp[tid], s);
    } else if (tid == 8) {
        float s = 0.f;
        #pragma unroll
        for (int w = 0; w < 8; w++) s += srz[w];
        atomicAdd(&g_rz, s);
    } else if (tid == 9) {
        float s = 0.f;
        #pragma unroll
        for (int w = 0; w < 8; w++) s += sent[w];
        atomicAdd(&g_ent, s);
    }
}

// ---------------- stage loaders (fp16 rows: 128 B data + 16 B pad) ----------------
__device__ __forceinline__ void g1_load(uint32_t ab, int s,
        const __half* __restrict__ Bp, const int* rowpr, int tid) {
    int buf = s % NSTG;
    int k0 = s * KC;
    uint32_t abase = ab + buf*STGB;
    uint32_t bbase = abase + ABYTES;
    #pragma unroll
    for (int i = 0; i < 4; i++) {
        int u = tid + 256*i; int r = u >> 3, sj = u & 7;
        int pr = rowpr[r];
        const __half* src = (pr >= 0) ? (g_xh + ((size_t)(pr >> 1))*ND + k0 + sj*8) : g_xh;
        cp16(abase + r*ROWB + sj*16, src, (pr >= 0) ? 16u : 0u);
    }
    #pragma unroll
    for (int i = 0; i < 4; i++) {
        int u = tid + 256*i; int r = u >> 3, sj = u & 7;
        cp16(bbase + r*ROWB + sj*16, Bp + (size_t)r*ND + k0 + sj*8, 16u);
    }
    CP_COMMIT();
}

__device__ __forceinline__ void g2_load(uint32_t ab, int s,
        int base_m, int nvalid, const __half* __restrict__ Bp, int tid) {
    int buf = s % NSTG;
    int k0 = s * KC;
    uint32_t abase = ab + buf*STGB;
    uint32_t bbase = abase + ABYTES;
    #pragma unroll
    for (int i = 0; i < 4; i++) {
        int u = tid + 256*i; int r = u >> 3, sj = u & 7;
        bool ok = (r < nvalid);
        const __half* src = g_h + (size_t)(base_m + (ok ? r : 0))*NH + k0 + sj*8;
        cp16(abase + r*ROWB + sj*16, src, ok ? 16u : 0u);
    }
    #pragma unroll
    for (int i = 0; i < 4; i++) {
        int u = tid + 256*i; int r = u >> 3, sj = u & 7;
        cp16(bbase + r*ROWB + sj*16, Bp + (size_t)r*NH + k0 + sj*8, 16u);
    }
    CP_COMMIT();
}

// ---------------- fragment load for one k16-step ----------------
__device__ __forceinline__ void ldfrags(uint32_t As, uint32_t Bs, int ks,
        int arow, uint32_t acol, int brow, uint32_t bcol,
        uint32_t af[4][4], uint32_t bf[2][4]) {
    uint32_t kb = (uint32_t)(ks*32);
    #pragma unroll
    for (int mt = 0; mt < 4; mt++)
        ldsm4(af[mt], As + (uint32_t)(arow + mt*16)*ROWB + kb + acol);
    #pragma unroll
    for (int p = 0; p < 2; p++)
        ldsm4(bf[p], Bs + (uint32_t)(brow + p*16)*ROWB + kb + bcol);
}

// ---------------- chunk compute: register double-buffered fragments ----------------
__device__ __forceinline__ void chunk_mma(uint32_t ab, int buf,
        int wm, int wn, int lane, float acc[4][4][4]) {
    uint32_t As = ab + buf*STGB;
    uint32_t Bs = As + ABYTES;
    int l7 = lane & 7;
    int arow = wm*64 + ((lane>>3)&1)*8 + l7;
    uint32_t acol = (uint32_t)((lane>>4)*16);
    int brow = wn*32 + ((lane>>4)&1)*8 + l7;
    uint32_t bcol = (uint32_t)(((lane>>3)&1)*16);

    uint32_t af[2][4][4], bf[2][2][4];
    ldfrags(As, Bs, 0, arow, acol, brow, bcol, af[0], bf[0]);
    #pragma unroll
    for (int ks = 0; ks < 4; ks++) {
        int cur = ks & 1, nxt = cur ^ 1;
        if (ks < 3)
            ldfrags(As, Bs, ks+1, arow, acol, brow, bcol, af[nxt], bf[nxt]);
        #pragma unroll
        for (int mt = 0; mt < 4; mt++)
            #pragma unroll
            for (int nt = 0; nt < 4; nt++)
                mma_f16(acc[mt][nt], af[cur][mt], &bf[cur][nt>>1][(nt&1)*2]);
    }
}

// ---------------- expert offset ----------------
__device__ __forceinline__ int expert_off(int e) {
    int s = 0;
    #pragma unroll
    for (int k = 0; k < NE; k++) if (k < e) s += g_cnt[k];
    return s;
}

// ---------------- GEMM1: h = h16(gelu(x @ W1 + b1)) ----------------
__global__ __launch_bounds__(256, 2) void gemm1_mma(const float* __restrict__ b1) {
    extern __shared__ char smem[];
    int e = blockIdx.z;
    int cnt = g_cnt[e];
    int m0 = blockIdx.y * TM;
    if (m0 >= cnt) return;
    int n0 = blockIdx.x * TN;
    int tid = threadIdx.x;
    int lane = tid & 31;
    int wm = (tid >> 5) & 1, wn = tid >> 6;
    uint32_t ab = smem_u32(smem) + SOFF;
    int* rowpr = (int*)smem;
    __shared__ int s_base;
    if (tid < TM) {
        int m = m0 + tid;
        rowpr[tid] = (m < cnt) ? g_list[e][m] : -1;
    }
    if (tid == 0) s_base = expert_off(e) + m0;
    __syncthreads();

    const __half* Bp = g_W1t + ((size_t)e*NH + (size_t)n0)*ND;
    const int T = ND / KC;  // 16

    float acc[4][4][4];
    #pragma unroll
    for (int a = 0; a < 4; a++)
        #pragma unroll
        for (int b = 0; b < 4; b++)
            #pragma unroll
            for (int c = 0; c < 4; c++) acc[a][b][c] = 0.f;

    for (int s = 0; s < NSTG-1; s++) g1_load(ab, s, Bp, rowpr, tid);

    for (int t = 0; t < T; t++) {
        if (t < T-1) CP_WAIT1(); else CP_WAIT0();
        __syncthreads();
        if (t + NSTG - 1 < T) g1_load(ab, t + NSTG - 1, Bp, rowpr, tid);
        chunk_mma(ab, t % NSTG, wm, wn, lane, acc);
    }

    int base_m = s_base;
    const float* bb = b1 + (size_t)e*NH + n0;
    #pragma unroll
    for (int mt = 0; mt < 4; mt++) {
        int r0 = wm*64 + mt*16 + (lane >> 2);
        #pragma unroll
        for (int half = 0; half < 2; half++) {
            int r = r0 + half*8;
            int pr = rowpr[r];
            if (pr < 0) continue;
            __half* hp = g_h + (size_t)(base_m + r)*NH + n0;
            #pragma unroll
            for (int nt = 0; nt < 4; nt++) {
                int cc = wn*32 + nt*8 + 2*(lane & 3);
                float v0 = acc[mt][nt][half*2+0] + bb[cc];
                float v1 = acc[mt][nt][half*2+1] + bb[cc+1];
                __half2 o = __floats2half2_rn(v0 * normcdff(v0), v1 * normcdff(v1));
                *(__half2*)(hp + cc) = o;
            }
        }
    }
}

// ---------------- GEMM2 (fused gating + combine): out += gate * (h @ W2 + b2) ----
__global__ __launch_bounds__(256, 2) void gemm2_mma(const float* __restrict__ b2,
                                                    float* __restrict__ out) {
    extern __shared__ char smem[];
    int e = blockIdx.z;
    int cnt = g_cnt[e];
    int m0 = blockIdx.y * TM;
    if (m0 >= cnt) return;
    int n0 = blockIdx.x * TN;
    int tid = threadIdx.x;
    int lane = tid & 31;
    int wm = (tid >> 5) & 1, wn = tid >> 6;
    uint32_t ab = smem_u32(smem) + SOFF;
    int* rowpr = (int*)smem;
    __shared__ int s_base;
    if (tid < TM) {
        int m = m0 + tid;
        rowpr[tid] = (m < cnt) ? g_list[e][m] : -1;
    }
    if (tid == 0) s_base = expert_off(e) + m0;
    __syncthreads();

    int base_m = s_base;
    int nvalid = cnt - m0; if (nvalid > TM) nvalid = TM;
    const __half* Bp = g_W2t + ((size_t)e*ND + (size_t)n0)*NH;
    const int T = NH / KC;  // 64

    float acc[4][4][4];
    #pragma unroll
    for (int a = 0; a < 4; a++)
        #pragma unroll
        for (int b = 0; b < 4; b++)
            #pragma unroll
            for (int c = 0; c < 4; c++) acc[a][b][c] = 0.f;

    for (int s = 0; s < NSTG-1; s++) g2_load(ab, s, base_m, nvalid, Bp, tid);

    for (int t = 0; t < T; t++) {
        if (t < T-1) CP_WAIT1(); else CP_WAIT0();
        __syncthreads();
        if (t + NSTG - 1 < T) g2_load(ab, t + NSTG - 1, base_m, nvalid, Bp, tid);
        chunk_mma(ab, t % NSTG, wm, wn, lane, acc);
    }

    const float* bb = b2 + (size_t)e*ND + n0;
    #pragma unroll
    for (int mt = 0; mt < 4; mt++) {
        int r0 = wm*64 + mt*16 + (lane >> 2);
        #pragma unroll
        for (int half = 0; half < 2; half++) {
            int r = r0 + half*8;
            int pr = rowpr[r];
            if (pr < 0) continue;
            float g = g_gate[pr];
            float* op = out + (size_t)(pr >> 1)*ND + n0;
            #pragma unroll
            for (int nt = 0; nt < 4; nt++) {
                int cc = wn*32 + nt*8 + 2*(lane & 3);
                atomicAdd(op + cc,     g * (acc[mt][nt][half*2+0] + bb[cc]));
                atomicAdd(op + cc + 1, g * (acc[mt][nt][half*2+1] + bb[cc+1]));
            }
        }
    }
}

// ---------------- finalize aux losses ----------------
__global__ void finalize_kernel(float* __restrict__ out) {
    const float invT = 1.f/(float)NTOK;
    float lb = 0.f;
    #pragma unroll
    for (int e = 0; e < NE; e++) {
        float im = g_imp[e]*invT - 1.f/NE;
        lb += im*im;
    }
    lb *= 1.f/NE;
    float rz  = g_rz  * invT;
    float ent = g_ent * invT;
    size_t o = (size_t)NTOK*ND;
    out[o+0] = lb;
    out[o+1] = rz;
    out[o+2] = ent;
    out[o+3] = lb + 0.001f*rz - 0.001f*ent;
}

// ---------------- launch ----------------
extern "C" void kernel_launch(void* const* d_in, const int* in_sizes, int n_in,
                              void* d_out, int out_size) {
    const float* x      = (const float*)d_in[0];
    const float* ctx    = (const float*)d_in[1];
    const float* qual   = (const float*)d_in[2];
    const float* rn_g   = (const float*)d_in[3];
    const float* rn_b   = (const float*)d_in[4];
    const float* cn_g   = (const float*)d_in[5];
    const float* cn_b   = (const float*)d_in[6];
    const float* ctx_W  = (const float*)d_in[7];
    const float* ctx_b  = (const float*)d_in[8];
    const float* q_W    = (const float*)d_in[9];
    const float* q_b    = (const float*)d_in[10];
    const float* r_W    = (const float*)d_in[11];
    const float* r_b    = (const float*)d_in[12];
    const float* temp   = (const float*)d_in[13];
    const float* W1     = (const float*)d_in[14];
    const float* b1     = (const float*)d_in[15];
    const float* W2     = (const float*)d_in[16];
    const float* b2     = (const float*)d_in[17];
    float* out = (float*)d_out;

    cudaFuncSetAttribute(gemm1_mma, cudaFuncAttributeMaxDynamicSharedMemorySize, DSMEM);
    cudaFuncSetAttribute(gemm2_mma, cudaFuncAttributeMaxDynamicSharedMemorySize, DSMEM);

    // our 4th launch is profiled -> router this round (instrumentation)
    prep_kernel<<<ND+1, 256>>>(ctx_W, r_W, ctx_b, q_W, q_b, r_b);         // 1
    transpose_w1<<<T1_BLKS, 256>>>(W1);                                   // 2
    transpose_w2<<<T2_BLKS, 256>>>(W2);                                   // 3
    router_kernel<<<NTOK/8, 256>>>(x, ctx, qual, rn_g, rn_b, cn_g, cn_b,
                                   r_W, temp, out);                       // 4 <- profiled
    gemm1_mma<<<dim3(NH/TN, NPAIR/TM, NE), 256, DSMEM>>>(b1);             // 5
    gemm2_mma<<<dim3(ND/TN, NPAIR/TM, NE), 256, DSMEM>>>(b2, out);        // 6
    finalize_kernel<<<1, 1>>>(out);                                       // 7
}

// round 17
// speedup vs baseline: 1.0007x; 1.0007x over previous
#include <cuda_runtime.h>
#include <cuda_fp16.h>
#include <math.h>
#include <stdint.h>

#define NB 4
#define NS 2048
#define ND 1024
#define NH 4096
#define NE 8
#define NTOK (NB*NS)      /* 8192 tokens */
#define NPAIR (NTOK*2)    /* 16384 (token,expert) pairs */

#define TM 128
#define TN 128
#define KC 64               /* K per stage (64 halfs = 128 B rows) */
#define NSTG 3
#define ROWB 144            /* padded row: 128 B data + 16 B pad */
#define ABYTES (128*ROWB)   /* 18432 B per matrix per stage */
#define STGB (2*ABYTES)
#define SOFF 512
#define DSMEM (SOFF + NSTG*STGB)   /* 111104 B -> 2 CTAs/SM */

// ---------------- device scratch (static allocations only) ----------------
__device__ float g_M[ND*NE];
__device__ float g_cvec[NE];
__device__ float g_qv[NE];
__device__ int   g_cnt[NE];
__device__ int   g_list[NE][NTOK];
__device__ float g_gate[NPAIR];
__device__ __half g_xh[(size_t)NTOK*ND];      // fp16 x (written by router)
__device__ __half g_W1t[(size_t)NE*NH*ND];    // W1^T  [e][n][k], fp16
__device__ __half g_W2t[(size_t)NE*ND*NH];    // W2^T  [e][n][k], fp16
__device__ __half g_h[(size_t)NPAIR*NH];      // hidden acts, fp16
__device__ float g_imp[NE];
__device__ float g_rz;
__device__ float g_ent;

// ---------------- helpers ----------------
__device__ __forceinline__ uint32_t smem_u32(const void* p) {
    uint32_t a;
    asm("{ .reg .u64 t; cvta.to.shared.u64 t, %1; cvt.u32.u64 %0, t; }"
        : "=r"(a) : "l"(p));
    return a;
}
__device__ __forceinline__ void cp16(uint32_t dst, const void* src, uint32_t bytes) {
    asm volatile("cp.async.cg.shared.global [%0], [%1], 16, %2;\n"
                 :: "r"(dst), "l"(src), "r"(bytes) : "memory");
}
#define CP_COMMIT() asm volatile("cp.async.commit_group;\n" ::: "memory")
#define CP_WAIT1()  asm volatile("cp.async.wait_group 1;\n" ::: "memory")
#define CP_WAIT0()  asm volatile("cp.async.wait_group 0;\n" ::: "memory")

__device__ __forceinline__ void mma_f16(float* c, const uint32_t* a, const uint32_t* b) {
    asm volatile("mma.sync.aligned.m16n8k16.row.col.f32.f16.f16.f32 "
        "{%0,%1,%2,%3}, {%4,%5,%6,%7}, {%8,%9}, {%0,%1,%2,%3};"
        : "+f"(c[0]), "+f"(c[1]), "+f"(c[2]), "+f"(c[3])
        : "r"(a[0]), "r"(a[1]), "r"(a[2]), "r"(a[3]), "r"(b[0]), "r"(b[1]));
}
__device__ __forceinline__ void ldsm4(uint32_t* r, uint32_t a) {
    asm volatile("ldmatrix.sync.aligned.m8n8.x4.shared.b16 {%0,%1,%2,%3}, [%4];"
        : "=r"(r[0]), "=r"(r[1]), "=r"(r[2]), "=r"(r[3]) : "r"(a));
}

// ---------------- prep reductions ----------------
__device__ __forceinline__ float blk_sum(float v, float* sred) {
    int tid = threadIdx.x;
    sred[tid] = v;
    __syncthreads();
    #pragma unroll
    for (int o = 128; o > 0; o >>= 1) {
        if (tid < o) sred[tid] += sred[tid + o];
        __syncthreads();
    }
    float r = sred[0];
    __syncthreads();
    return r;
}

#define T1_BLKS (NE*(ND/64)*(NH/32))   /* 16384 */
#define T2_BLKS (NE*(NH/64)*(ND/32))   /* 16384 */

__global__ __launch_bounds__(256) void prep_kernel(
        const float* __restrict__ ctx_W, const float* __restrict__ r_W,
        const float* __restrict__ ctx_b, const float* __restrict__ q_W,
        const float* __restrict__ q_b,  const float* __restrict__ r_b) {
    __shared__ float sred[256];
    int b = blockIdx.x;
    int tid = threadIdx.x;
    if (b == 0) {
        if (tid < NE) { g_cnt[tid] = 0; g_imp[tid] = 0.f; }
        if (tid == 0) { g_rz = 0.f; g_ent = 0.f; }
        float pc[NE], pq[NE];
        #pragma unroll
        for (int e = 0; e < NE; e++) { pc[e] = 0.f; pq[e] = 0.f; }
        for (int d = tid; d < ND; d += 256) {
            float cb = ctx_b[d] + q_b[d];
            float qw = q_W[d];
            #pragma unroll
            for (int e = 0; e < NE; e++) {
                pc[e] += cb * r_W[d*NE + e];
                pq[e] += qw * r_W[d*NE + e];
            }
        }
        #pragma unroll
        for (int e = 0; e < NE; e++) {
            float vc = blk_sum(pc[e], sred);
            float vq = blk_sum(pq[e], sred);
            if (tid == 0) { g_cvec[e] = vc + r_b[e]; g_qv[e] = vq; }
        }
    } else {
        int j = b - 1;
        float part[NE];
        #pragma unroll
        for (int e = 0; e < NE; e++) part[e] = 0.f;
        for (int d = tid; d < ND; d += 256) {
            float w = ctx_W[(size_t)j*ND + d];
            #pragma unroll
            for (int e = 0; e < NE; e++) part[e] += w * r_W[d*NE + e];
        }
        #pragma unroll
        for (int e = 0; e < NE; e++) {
            float v = blk_sum(part[e], sred);
            if (tid == 0) g_M[j*NE + e] = v;
        }
    }
}

// ---------------- transposes (64 S-rows x 32 S-cols tile) ----------------
__device__ __forceinline__ void transpose_tile(const float* S, __half* D,
                                               int R, int C, int r0, int c0,
                                               int tid) {
    __shared__ float t[64][33];
    int lane = tid & 31, w = tid >> 5;
    #pragma unroll
    for (int i = 0; i < 8; i++)
        t[w*8 + i][lane] = S[(size_t)(r0 + w*8 + i)*C + c0 + lane];
    __syncthreads();
    #pragma unroll
    for (int jj = 0; jj < 4; jj++) {
        int j = w + jj*8;
        __half2 v = __floats2half2_rn(t[2*lane][j], t[2*lane + 1][j]);
        *(__half2*)(D + (size_t)(c0 + j)*R + r0 + 2*lane) = v;
    }
}

__global__ __launch_bounds__(256) void transpose_w1(const float* __restrict__ W1) {
    int i = blockIdx.x;
    int e = i >> 11;
    int rem = i & 2047;         // 128 cblk x 16 rblk (R=ND=1024, C=NH)
    int c0 = (rem & 127) * 32;
    int r0 = (rem >> 7) * 64;
    transpose_tile(W1 + (size_t)e*ND*NH, g_W1t + (size_t)e*ND*NH,
                   ND, NH, r0, c0, threadIdx.x);
}

__global__ __launch_bounds__(256) void transpose_w2(const float* __restrict__ W2) {
    int i = blockIdx.x;
    int e = i >> 11;
    int rem = i & 2047;         // 32 cblk x 64 rblk (R=NH=4096, C=ND)
    int c0 = (rem & 31) * 32;
    int r0 = (rem >> 5) * 64;
    transpose_tile(W2 + (size_t)e*NH*ND, g_W2t + (size_t)e*NH*ND,
                   NH, ND, r0, c0, threadIdx.x);
}

// ---------------- router: one BLOCK per token (low regs, high occupancy) -------
__global__ __launch_bounds__(256) void router_kernel(
        const float* __restrict__ x, const float* __restrict__ ctx,
        const float* __restrict__ quality,
        const float* __restrict__ rn_g, const float* __restrict__ rn_b,
        const float* __restrict__ cn_g, const float* __restrict__ cn_b,
        const float* __restrict__ r_W, const float* __restrict__ temp_p,
        float* __restrict__ out) {
    int t = blockIdx.x;
    int tid = threadIdx.x, lane = tid & 31, wid = tid >> 5;

    float4 xv = ((const float4*)(x   + (size_t)t*ND))[tid];
    float4 cv = ((const float4*)(ctx + (size_t)t*ND))[tid];

    // zero output row (gemm2 accumulates atomically)
    ((float4*)(out + (size_t)t*ND))[tid] = make_float4(0.f,0.f,0.f,0.f);

    // fp16 copy of x
    {
        __half2 h0 = __floats2half2_rn(xv.x, xv.y);
        __half2 h1 = __floats2half2_rn(xv.z, xv.w);
        uint2 o = make_uint2(*(uint32_t*)&h0, *(uint32_t*)&h1);
        *(uint2*)(g_xh + (size_t)t*ND + tid*4) = o;
    }

    float sx  = xv.x + xv.y + xv.z + xv.w;
    float sxx = xv.x*xv.x + xv.y*xv.y + xv.z*xv.z + xv.w*xv.w;
    float sc  = cv.x + cv.y + cv.z + cv.w;
    float scc = cv.x*cv.x + cv.y*cv.y + cv.z*cv.z + cv.w*cv.w;
    #pragma unroll
    for (int o = 16; o; o >>= 1) {
        sx  += __shfl_xor_sync(0xFFFFFFFFu, sx,  o);
        sxx += __shfl_xor_sync(0xFFFFFFFFu, sxx, o);
        sc  += __shfl_xor_sync(0xFFFFFFFFu, sc,  o);
        scc += __shfl_xor_sync(0xFFFFFFFFu, scc, o);
    }
    __shared__ float ws[8][4];
    __shared__ float lw[8][8];
    __shared__ float lg_s[8];
    if (lane == 0) { ws[wid][0]=sx; ws[wid][1]=sxx; ws[wid][2]=sc; ws[wid][3]=scc; }
    __syncthreads();
    float fx=0, fxx=0, fc=0, fcc=0;
    #pragma unroll
    for (int w = 0; w < 8; w++) {
        fx += ws[w][0]; fxx += ws[w][1]; fc += ws[w][2]; fcc += ws[w][3];
    }
    float mu_x = fx*(1.f/ND), mu_c = fc*(1.f/ND);
    float rs_x = rsqrtf(fxx*(1.f/ND) - mu_x*mu_x + 1e-5f);
    float rs_c = rsqrtf(fcc*(1.f/ND) - mu_c*mu_c + 1e-5f);

    float part[NE];
    #pragma unroll
    for (int e = 0; e < NE; e++) part[e] = 0.f;
    float xa[4] = {xv.x, xv.y, xv.z, xv.w};
    float ca[4] = {cv.x, cv.y, cv.z, cv.w};
    #pragma unroll
    for (int i = 0; i < 4; i++) {
        int d = tid*4 + i;
        float nx = (xa[i]-mu_x)*rs_x*rn_g[d] + rn_b[d];
        float nc = (ca[i]-mu_c)*rs_c*cn_g[d] + cn_b[d];
        const float* rw = r_W + d*NE;
        const float* mm = g_M + d*NE;
        #pragma unroll
        for (int e = 0; e < NE; e++) part[e] += nx*rw[e] + nc*mm[e];
    }
    #pragma unroll
    for (int e = 0; e < NE; e++)
        #pragma unroll
        for (int o = 16; o; o >>= 1)
            part[e] += __shfl_xor_sync(0xFFFFFFFFu, part[e], o);
    if (lane == 0)
        #pragma unroll
        for (int e = 0; e < NE; e++) lw[wid][e] = part[e];
    __syncthreads();
    if (tid < 8) {
        float s = 0.f;
        #pragma unroll
        for (int w = 0; w < 8; w++) s += lw[w][tid];
        lg_s[tid] = s;
    }
    __syncthreads();

    if (tid == 0) {
        float temp = fmaxf(temp_p[0], 0.25f);
        float q = quality[t / NS];
        float lg[NE];
        #pragma unroll
        for (int e = 0; e < NE; e++)
            lg[e] = (lg_s[e] + g_cvec[e] + q*g_qv[e]) / temp;

        int i1 = 0;
        #pragma unroll
        for (int e = 1; e < NE; e++) if (lg[e] > lg[i1]) i1 = e;
        int i2 = (i1 == 0) ? 1 : 0;
        #pragma unroll
        for (int e = 0; e < NE; e++) {
            if (e == i1 || e == i2) continue;
            if (lg[e] > lg[i2]) i2 = e;
        }

        float mx = lg[0];
        #pragma unroll
        for (int e = 1; e < NE; e++) mx = fmaxf(mx, lg[e]);
        float se = 0.f;
        #pragma unroll
        for (int e = 0; e < NE; e++) se += expf(lg[e]-mx);
        float lse = mx + logf(se);
        float inv_se = 1.f/se;
        float ent = 0.f;
        #pragma unroll
        for (int e = 0; e < NE; e++) {
            float p = expf(lg[e]-mx)*inv_se;
            atomicAdd(&g_imp[e], p);
            ent -= p * (lg[e]-lse);
        }
        atomicAdd(&g_rz, lse*lse);
        atomicAdd(&g_ent, ent);

        float ex = expf(lg[i2]-lg[i1]);
        float inv = 1.f/(1.f+ex);
        g_gate[2*t]   = inv;
        g_gate[2*t+1] = ex*inv;
        int p1 = atomicAdd(&g_cnt[i1], 1);
        g_list[i1][p1] = 2*t;
        int p2 = atomicAdd(&g_cnt[i2], 1);
        g_list[i2][p2] = 2*t+1;
    }
}

// ---------------- stage loaders (fp16 rows: 128 B data + 16 B pad) ----------------
__device__ __forceinline__ void g1_load(uint32_t ab, int s,
        const __half* __restrict__ Bp, const int* rowpr, int tid) {
    int buf = s % NSTG;
    int k0 = s * KC;
    uint32_t abase = ab + buf*STGB;
    uint32_t bbase = abase + ABYTES;
    #pragma unroll
    for (int i = 0; i < 4; i++) {
        int u = tid + 256*i; int r = u >> 3, sj = u & 7;
        int pr = rowpr[r];
        const __half* src = (pr >= 0) ? (g_xh + ((size_t)(pr >> 1))*ND + k0 + sj*8) : g_xh;
        cp16(abase + r*ROWB + sj*16, src, (pr >= 0) ? 16u : 0u);
    }
    #pragma unroll
    for (int i = 0; i < 4; i++) {
        int u = tid + 256*i; int r = u >> 3, sj = u & 7;
        cp16(bbase + r*ROWB + sj*16, Bp + (size_t)r*ND + k0 + sj*8, 16u);
    }
    CP_COMMIT();
}

__device__ __forceinline__ void g2_load(uint32_t ab, int s,
        int base_m, int nvalid, const __half* __restrict__ Bp, int tid) {
    int buf = s % NSTG;
    int k0 = s * KC;
    uint32_t abase = ab + buf*STGB;
    uint32_t bbase = abase + ABYTES;
    #pragma unroll
    for (int i = 0; i < 4; i++) {
        int u = tid + 256*i; int r = u >> 3, sj = u & 7;
        bool ok = (r < nvalid);
        const __half* src = g_h + (size_t)(base_m + (ok ? r : 0))*NH + k0 + sj*8;
        cp16(abase + r*ROWB + sj*16, src, ok ? 16u : 0u);
    }
    #pragma unroll
    for (int i = 0; i < 4; i++) {
        int u = tid + 256*i; int r = u >> 3, sj = u & 7;
        cp16(bbase + r*ROWB + sj*16, Bp + (size_t)r*NH + k0 + sj*8, 16u);
    }
    CP_COMMIT();
}

// ---------------- fragment load for one k16-step ----------------
__device__ __forceinline__ void ldfrags(uint32_t As, uint32_t Bs, int ks,
        int arow, uint32_t acol, int brow, uint32_t bcol,
        uint32_t af[4][4], uint32_t bf[2][4]) {
    uint32_t kb = (uint32_t)(ks*32);
    #pragma unroll
    for (int mt = 0; mt < 4; mt++)
        ldsm4(af[mt], As + (uint32_t)(arow + mt*16)*ROWB + kb + acol);
    #pragma unroll
    for (int p = 0; p < 2; p++)
        ldsm4(bf[p], Bs + (uint32_t)(brow + p*16)*ROWB + kb + bcol);
}

// ---------------- chunk compute: register double-buffered fragments ----------------
__device__ __forceinline__ void chunk_mma(uint32_t ab, int buf,
        int wm, int wn, int lane, float acc[4][4][4]) {
    uint32_t As = ab + buf*STGB;
    uint32_t Bs = As + ABYTES;
    int l7 = lane & 7;
    int arow = wm*64 + ((lane>>3)&1)*8 + l7;
    uint32_t acol = (uint32_t)((lane>>4)*16);
    int brow = wn*32 + ((lane>>4)&1)*8 + l7;
    uint32_t bcol = (uint32_t)(((lane>>3)&1)*16);

    uint32_t af[2][4][4], bf[2][2][4];
    ldfrags(As, Bs, 0, arow, acol, brow, bcol, af[0], bf[0]);
    #pragma unroll
    for (int ks = 0; ks < 4; ks++) {
        int cur = ks & 1, nxt = cur ^ 1;
        if (ks < 3)
            ldfrags(As, Bs, ks+1, arow, acol, brow, bcol, af[nxt], bf[nxt]);
        #pragma unroll
        for (int mt = 0; mt < 4; mt++)
            #pragma unroll
            for (int nt = 0; nt < 4; nt++)
                mma_f16(acc[mt][nt], af[cur][mt], &bf[cur][nt>>1][(nt&1)*2]);
    }
}

// ---------------- expert offset ----------------
__device__ __forceinline__ int expert_off(int e) {
    int s = 0;
    #pragma unroll
    for (int k = 0; k < NE; k++) if (k < e) s += g_cnt[k];
    return s;
}

// ---------------- GEMM1: h = h16(gelu(x @ W1 + b1)) ----------------
__global__ __launch_bounds__(256, 2) void gemm1_mma(const float* __restrict__ b1) {
    extern __shared__ char smem[];
    int e = blockIdx.z;
    int cnt = g_cnt[e];
    int m0 = blockIdx.y * TM;
    if (m0 >= cnt) return;
    int n0 = blockIdx.x * TN;
    int tid = threadIdx.x;
    int lane = tid & 31;
    int wm = (tid >> 5) & 1, wn = tid >> 6;
    uint32_t ab = smem_u32(smem) + SOFF;
    int* rowpr = (int*)smem;
    __shared__ int s_base;
    if (tid < TM) {
        int m = m0 + tid;
        rowpr[tid] = (m < cnt) ? g_list[e][m] : -1;
    }
    if (tid == 0) s_base = expert_off(e) + m0;
    __syncthreads();

    const __half* Bp = g_W1t + ((size_t)e*NH + (size_t)n0)*ND;
    const int T = ND / KC;  // 16

    float acc[4][4][4];
    #pragma unroll
    for (int a = 0; a < 4; a++)
        #pragma unroll
        for (int b = 0; b < 4; b++)
            #pragma unroll
            for (int c = 0; c < 4; c++) acc[a][b][c] = 0.f;

    for (int s = 0; s < NSTG-1; s++) g1_load(ab, s, Bp, rowpr, tid);

    for (int t = 0; t < T; t++) {
        if (t < T-1) CP_WAIT1(); else CP_WAIT0();
        __syncthreads();
        if (t + NSTG - 1 < T) g1_load(ab, t + NSTG - 1, Bp, rowpr, tid);
        chunk_mma(ab, t % NSTG, wm, wn, lane, acc);
    }

    int base_m = s_base;
    const float* bb = b1 + (size_t)e*NH + n0;
    #pragma unroll
    for (int mt = 0; mt < 4; mt++) {
        int r0 = wm*64 + mt*16 + (lane >> 2);
        #pragma unroll
        for (int half = 0; half < 2; half++) {
            int r = r0 + half*8;
            int pr = rowpr[r];
            if (pr < 0) continue;
            __half* hp = g_h + (size_t)(base_m + r)*NH + n0;
            #pragma unroll
            for (int nt = 0; nt < 4; nt++) {
                int cc = wn*32 + nt*8 + 2*(lane & 3);
                float v0 = acc[mt][nt][half*2+0] + bb[cc];
                float v1 = acc[mt][nt][half*2+1] + bb[cc+1];
                __half2 o = __floats2half2_rn(v0 * normcdff(v0), v1 * normcdff(v1));
                *(__half2*)(hp + cc) = o;
            }
        }
    }
}

// ---------------- GEMM2 (fused gating + combine): out += gate * (h @ W2 + b2) ----
__global__ __launch_bounds__(256, 2) void gemm2_mma(const float* __restrict__ b2,
                                                    float* __restrict__ out) {
    extern __shared__ char smem[];
    int e = blockIdx.z;
    int cnt = g_cnt[e];
    int m0 = blockIdx.y * TM;
    if (m0 >= cnt) return;
    int n0 = blockIdx.x * TN;
    int tid = threadIdx.x;
    int lane = tid & 31;
    int wm = (tid >> 5) & 1, wn = tid >> 6;
    uint32_t ab = smem_u32(smem) + SOFF;
    int* rowpr = (int*)smem;
    __shared__ int s_base;
    if (tid < TM) {
        int m = m0 + tid;
        rowpr[tid] = (m < cnt) ? g_list[e][m] : -1;
    }
    if (tid == 0) s_base = expert_off(e) + m0;
    __syncthreads();

    int base_m = s_base;
    int nvalid = cnt - m0; if (nvalid > TM) nvalid = TM;
    const __half* Bp = g_W2t + ((size_t)e*ND + (size_t)n0)*NH;
    const int T = NH / KC;  // 64

    float acc[4][4][4];
    #pragma unroll
    for (int a = 0; a < 4; a++)
        #pragma unroll
        for (int b = 0; b < 4; b++)
            #pragma unroll
            for (int c = 0; c < 4; c++) acc[a][b][c] = 0.f;

    for (int s = 0; s < NSTG-1; s++) g2_load(ab, s, base_m, nvalid, Bp, tid);

    for (int t = 0; t < T; t++) {
        if (t < T-1) CP_WAIT1(); else CP_WAIT0();
        __syncthreads();
        if (t + NSTG - 1 < T) g2_load(ab, t + NSTG - 1, base_m, nvalid, Bp, tid);
        chunk_mma(ab, t % NSTG, wm, wn, lane, acc);
    }

    const float* bb = b2 + (size_t)e*ND + n0;
    #pragma unroll
    for (int mt = 0; mt < 4; mt++) {
        int r0 = wm*64 + mt*16 + (lane >> 2);
        #pragma unroll
        for (int half = 0; half < 2; half++) {
            int r = r0 + half*8;
            int pr = rowpr[r];
            if (pr < 0) continue;
            float g = g_gate[pr];
            float* op = out + (size_t)(pr >> 1)*ND + n0;
            #pragma unroll
            for (int nt = 0; nt < 4; nt++) {
                int cc = wn*32 + nt*8 + 2*(lane & 3);
                atomicAdd(op + cc,     g * (acc[mt][nt][half*2+0] + bb[cc]));
                atomicAdd(op + cc + 1, g * (acc[mt][nt][half*2+1] + bb[cc+1]));
            }
        }
    }
}

// ---------------- finalize aux losses ----------------
__global__ void finalize_kernel(float* __restrict__ out) {
    const float invT = 1.f/(float)NTOK;
    float lb = 0.f;
    #pragma unroll
    for (int e = 0; e < NE; e++) {
        float im = g_imp[e]*invT - 1.f/NE;
        lb += im*im;
    }
    lb *= 1.f/NE;
    float rz  = g_rz  * invT;
    float ent = g_ent * invT;
    size_t o = (size_t)NTOK*ND;
    out[o+0] = lb;
    out[o+1] = rz;
    out[o+2] = ent;
    out[o+3] = lb + 0.001f*rz - 0.001f*ent;
}

// ---------------- launch ----------------
extern "C" void kernel_launch(void* const* d_in, const int* in_sizes, int n_in,
                              void* d_out, int out_size) {
    const float* x      = (const float*)d_in[0];
    const float* ctx    = (const float*)d_in[1];
    const float* qual   = (const float*)d_in[2];
    const float* rn_g   = (const float*)d_in[3];
    const float* rn_b   = (const float*)d_in[4];
    const float* cn_g   = (const float*)d_in[5];
    const float* cn_b   = (const float*)d_in[6];
    const float* ctx_W  = (const float*)d_in[7];
    const float* ctx_b  = (const float*)d_in[8];
    const float* q_W    = (const float*)d_in[9];
    const float* q_b    = (const float*)d_in[10];
    const float* r_W    = (const float*)d_in[11];
    const float* r_b    = (const float*)d_in[12];
    const float* temp   = (const float*)d_in[13];
    const float* W1     = (const float*)d_in[14];
    const float* b1     = (const float*)d_in[15];
    const float* W2     = (const float*)d_in[16];
    const float* b2     = (const float*)d_in[17];
    float* out = (float*)d_out;

    cudaFuncSetAttribute(gemm1_mma, cudaFuncAttributeMaxDynamicSharedMemorySize, DSMEM);
    cudaFuncSetAttribute(gemm2_mma, cudaFuncAttributeMaxDynamicSharedMemorySize, DSMEM);

    // our 4th launch is profiled -> router (verify the fix)
    prep_kernel<<<ND+1, 256>>>(ctx_W, r_W, ctx_b, q_W, q_b, r_b);         // 1
    transpose_w1<<<T1_BLKS, 256>>>(W1);                                   // 2
    transpose_w2<<<T2_BLKS, 256>>>(W2);                                   // 3
    router_kernel<<<NTOK, 256>>>(x, ctx, qual, rn_g, rn_b, cn_g, cn_b,
                                 r_W, temp, out);                         // 4 <- profiled
    gemm1_mma<<<dim3(NH/TN, NPAIR/TM, NE), 256, DSMEM>>>(b1);             // 5
    gemm2_mma<<<dim3(ND/TN, NPAIR/TM, NE), 256, DSMEM>>>(b2, out);        // 6
    finalize_kernel<<<1, 1>>>(out);                                       // 7
}